// round 9
// baseline (speedup 1.0000x reference)
#include <cuda_runtime.h>
#include <cstdint>

// ---------------------------------------------------------------------------
// HierarchicalDownTopFusion — fused tf32 mma.sync, pipelined (R8).
//
//   g_m   = gelu(LN(pool4(small, adj[m]) @ W1 + b1))           m = 0..3
//   h2    = mean(medium) @ W1' + (Sum_m g_m) @ (0.25*W2@W1') + (b2@W1' + b1')
//   out   = global + gelu(LN(h2)) @ W2' + b2'
//
// R8: 512 threads (16 warps, 4/SMSP) on the same 64-row tile; warp tile
//     32x32 -> 32 accumulator regs/thread, <=128 regs total so the full
//     register file supports 4 warps/scheduler. Structure otherwise = R6.
// ---------------------------------------------------------------------------

#define B_ROWS 65536
#define IN_DIM 768
#define HID    256
#define TM     64
#define NTHR   512
#define AP     36          // abuf pitch
#define WP     36          // wbuf pitch
#define GP     260         // gsum pitch
#define NC1    (IN_DIM/32) // 24
#define NC2    (HID/32)    // 8

// smem: gsum[64][260] + 2*abuf[64][36] + 2*wbuf[256][36] + prm 6*256 + scratch 1024
#define SMEM_FLOATS (TM*GP + 2*TM*AP + 2*256*WP + 6*256 + 1024)
#define SMEM_BYTES  (SMEM_FLOATS * 4)   // 168960

__device__ __align__(16) float g_W1t [HID * IN_DIM];  // sm_w1^T  (tf32)
__device__ __align__(16) float g_W1pt[HID * IN_DIM];  // mg_w1^T  (tf32)
__device__ __align__(16) float g_W2pt[IN_DIM * HID];  // mg_w2^T  (tf32)
__device__ __align__(16) float g_Cs  [HID * HID];     // (0.25*sm_w2@mg_w1)^T (tf32)
__device__ __align__(16) float g_bias2[HID];          // sm_b2@mg_w1 + mg_b1

__constant__ int c_adj[4][4] = {{0,1,3,4},{1,2,4,5},{3,4,6,7},{4,5,7,8}};

__device__ __forceinline__ float to_tf32(float x){
    uint32_t u; asm("cvt.rna.tf32.f32 %0, %1;" : "=r"(u) : "f"(x));
    return __uint_as_float(u);
}

__device__ __forceinline__ void mma8(float* d, const uint32_t* a, uint32_t b0, uint32_t b1){
    asm("mma.sync.aligned.m16n8k8.row.col.f32.tf32.tf32.f32 "
        "{%0,%1,%2,%3}, {%4,%5,%6,%7}, {%8,%9}, {%0,%1,%2,%3};\n"
        : "+f"(d[0]), "+f"(d[1]), "+f"(d[2]), "+f"(d[3])
        : "r"(a[0]), "r"(a[1]), "r"(a[2]), "r"(a[3]), "r"(b0), "r"(b1));
}

__device__ __forceinline__ uint32_t smem_u32(const void* p){
    return (uint32_t)__cvta_generic_to_shared(p);
}
__device__ __forceinline__ void cpa16(uint32_t dst, const void* src){
    asm volatile("cp.async.ca.shared.global [%0], [%1], 16;\n" :: "r"(dst), "l"(src));
}
#define CP_COMMIT asm volatile("cp.async.commit_group;\n")
#define CP_WAIT0  asm volatile("cp.async.wait_group 0;\n")

// ------------------------------- prep kernels ------------------------------

__global__ void prep_transpose(const float* __restrict__ smw1,
                               const float* __restrict__ mgw1,
                               const float* __restrict__ mgw2){
    int k = blockIdx.x;     // 0..767
    int n = threadIdx.x;    // 0..255
    g_W1t [n*IN_DIM + k] = to_tf32(smw1[k*HID + n]);
    g_W1pt[n*IN_DIM + k] = to_tf32(mgw1[k*HID + n]);
    g_W2pt[k*HID + n]    = to_tf32(mgw2[n*IN_DIM + k]);
}

__global__ void prep_C(const float* __restrict__ smw2, const float* __restrict__ mgw1){
    int k = blockIdx.x;     // 0..255
    int n = threadIdx.x;    // 0..255
    float acc = 0.f;
    for (int t = 0; t < IN_DIM; t++)
        acc += smw2[k*IN_DIM + t] * mgw1[t*HID + n];
    g_Cs[n*HID + k] = to_tf32(0.25f * acc);
}

__global__ void prep_bias(const float* __restrict__ smb2, const float* __restrict__ mgw1,
                          const float* __restrict__ mgb1){
    int n = threadIdx.x;
    float acc = mgb1[n];
    for (int t = 0; t < IN_DIM; t++)
        acc += smb2[t] * mgw1[t*HID + n];
    g_bias2[n] = acc;
}

// ------------------------------- device helpers ----------------------------

// warp tile 32(M) x 32(N): d[2][4][4]
template<bool CVT, int APITCH>
__device__ __forceinline__ void mma_chunk(float d[2][4][4], const float* __restrict__ A,
                                          const float* __restrict__ W,
                                          int wm, int wn, int gid, int tig){
#pragma unroll
    for (int ks = 0; ks < 4; ks++){
        uint32_t a[2][4];
#pragma unroll
        for (int mt = 0; mt < 2; mt++){
            int r = wm*32 + mt*16 + gid;
            int c = ks*8 + tig;
            float a0 = A[r*APITCH + c];
            float a1 = A[(r+8)*APITCH + c];
            float a2 = A[r*APITCH + c + 4];
            float a3 = A[(r+8)*APITCH + c + 4];
            if (CVT){ a0 = to_tf32(a0); a1 = to_tf32(a1); a2 = to_tf32(a2); a3 = to_tf32(a3); }
            a[mt][0] = __float_as_uint(a0); a[mt][1] = __float_as_uint(a1);
            a[mt][2] = __float_as_uint(a2); a[mt][3] = __float_as_uint(a3);
        }
#pragma unroll
        for (int nt = 0; nt < 4; nt++){
            int n  = wn*32 + nt*8 + gid;
            int kk = ks*8 + tig;
            uint32_t b0 = __float_as_uint(W[n*WP + kk]);
            uint32_t b1 = __float_as_uint(W[n*WP + kk + 4]);
            mma8(d[0][nt], a[0], b0, b1);
            mma8(d[1][nt], a[1], b0, b1);
        }
    }
}

__device__ __forceinline__ void zero_d(float d[2][4][4]){
#pragma unroll
    for (int mt = 0; mt < 2; mt++)
#pragma unroll
    for (int nt = 0; nt < 4; nt++)
#pragma unroll
    for (int j = 0; j < 4; j++) d[mt][nt][j] = 0.f;
}

// stage one [256 x 32] weight chunk into wbuf via cp.async (weights pre-tf32)
__device__ __forceinline__ void stage_w(float* wbuf, const float* __restrict__ Wg,
                                        int rowstride, int kc, int tid){
    uint32_t wb = smem_u32(wbuf);
#pragma unroll
    for (int i = 0; i < 4; i++){
        int idx = i*NTHR + tid;
        int n = idx >> 3, g = idx & 7;
        cpa16(wb + (uint32_t)(n*WP + g*4)*4u, Wg + n*rowstride + kc*32 + g*4);
    }
}

// raw loads for one pooled [64 x 32] A chunk (4 slabs); 1 float4 per thread
struct PoolLd { float4 v[4]; };

__device__ __forceinline__ void pool_ld(PoolLd& P, const float4* __restrict__ S4,
                                        int i0,int i1,int i2,int i3,
                                        int row0, int kc, int tid){
    const int SLAB = B_ROWS * (IN_DIM/4);
    int r = tid >> 3, kk = tid & 7;
    int ro = (row0 + r)*(IN_DIM/4) + kc*8 + kk;
    P.v[0] = __ldg(S4 + i0*SLAB + ro);
    P.v[1] = __ldg(S4 + i1*SLAB + ro);
    P.v[2] = __ldg(S4 + i2*SLAB + ro);
    P.v[3] = __ldg(S4 + i3*SLAB + ro);
}

__device__ __forceinline__ void pool_st(const PoolLd& P, float* abuf, int tid){
    float4* ab4 = (float4*)abuf;
    int r = tid >> 3, kk = tid & 7;
    float4 o;
    o.x = to_tf32(0.25f*(P.v[0].x + P.v[1].x + P.v[2].x + P.v[3].x));
    o.y = to_tf32(0.25f*(P.v[0].y + P.v[1].y + P.v[2].y + P.v[3].y));
    o.z = to_tf32(0.25f*(P.v[0].z + P.v[1].z + P.v[2].z + P.v[3].z));
    o.w = to_tf32(0.25f*(P.v[0].w + P.v[1].w + P.v[2].w + P.v[3].w));
    ab4[r*9 + kk] = o;
}

// GEMM over K=768 with pooled A, double-buffered A (reg prefetch) + W (cp.async)
__device__ __forceinline__ void gemm_pooled(float d[2][4][4],
    const float4* __restrict__ S4, int i0,int i1,int i2,int i3, int row0,
    const float* __restrict__ Wg,
    float* ab0, float* ab1, float* wb0, float* wb1,
    int wm,int wn,int gid,int tig,int tid)
{
    PoolLd P;
    stage_w(wb0, Wg, IN_DIM, 0, tid);
    CP_COMMIT;
    pool_ld(P, S4, i0,i1,i2,i3, row0, 0, tid);
    pool_st(P, ab0, tid);
    CP_WAIT0;
    __syncthreads();
#pragma unroll 1
    for (int kc = 0; kc < NC1; kc++){
        float* ac = (kc & 1) ? ab1 : ab0;
        float* wc = (kc & 1) ? wb1 : wb0;
        if (kc + 1 < NC1){
            float* wnx = (kc & 1) ? wb0 : wb1;
            stage_w(wnx, Wg, IN_DIM, kc+1, tid);
            CP_COMMIT;
            pool_ld(P, S4, i0,i1,i2,i3, row0, kc+1, tid);
            mma_chunk<false, AP>(d, ac, wc, wm, wn, gid, tig);
            float* anx = (kc & 1) ? ab0 : ab1;
            pool_st(P, anx, tid);
            CP_WAIT0;
        } else {
            mma_chunk<false, AP>(d, ac, wc, wm, wn, gid, tig);
        }
        __syncthreads();
    }
}

// GEMM with A resident in smem (gsum), weights double-buffered
template<bool CVT>
__device__ __forceinline__ void gemm_smemA(float d[2][4][4], const float* Asm,
    const float* __restrict__ Wg, int rowstride, int nchunks,
    float* wb0, float* wb1, int wm,int wn,int gid,int tig,int tid)
{
    stage_w(wb0, Wg, rowstride, 0, tid);
    CP_COMMIT;
    CP_WAIT0;
    __syncthreads();
#pragma unroll 1
    for (int kc = 0; kc < nchunks; kc++){
        float* wc = (kc & 1) ? wb1 : wb0;
        if (kc + 1 < nchunks){
            float* wnx = (kc & 1) ? wb0 : wb1;
            stage_w(wnx, Wg, rowstride, kc+1, tid);
            CP_COMMIT;
        }
        mma_chunk<CVT, GP>(d, Asm + kc*32, wc, wm, wn, gid, tig);
        if (kc + 1 < nchunks) CP_WAIT0;
        __syncthreads();
    }
}

// In-register LayerNorm + exact GELU epilogue (warp covers 32 of 256 cols,
// so each row's stats gather 8 warp-partials through smem scratch).
// ACC:  gsum += gelu(LN(d+b))      (fp32 accumulate across mediums)
// !ACC: gsum  = tf32(gelu(LN(d+b))) (g2, pre-rounded A for final GEMM)
template<bool ACC>
__device__ __forceinline__ void ln_gelu_reg(const float d[2][4][4], float* gsum,
        float* scratch,
        const float* bP, const float* gP, const float* beP,
        int wm,int wn,int gid,int tig)
{
    float bc[4][2];
#pragma unroll
    for (int nt = 0; nt < 4; nt++){
        int c = wn*32 + nt*8 + tig*2;
        bc[nt][0] = bP[c]; bc[nt][1] = bP[c+1];
    }
    float s1[2][2] = {{0,0},{0,0}}, s2[2][2] = {{0,0},{0,0}};
#pragma unroll
    for (int mt = 0; mt < 2; mt++)
#pragma unroll
    for (int nt = 0; nt < 4; nt++){
        float v0 = d[mt][nt][0] + bc[nt][0], v1 = d[mt][nt][1] + bc[nt][1];
        float v2 = d[mt][nt][2] + bc[nt][0], v3 = d[mt][nt][3] + bc[nt][1];
        s1[mt][0] += v0 + v1;  s2[mt][0] += v0*v0 + v1*v1;
        s1[mt][1] += v2 + v3;  s2[mt][1] += v2*v2 + v3*v3;
    }
#pragma unroll
    for (int mt = 0; mt < 2; mt++)
#pragma unroll
    for (int h = 0; h < 2; h++){
        s1[mt][h] += __shfl_xor_sync(0xffffffffu, s1[mt][h], 1);
        s2[mt][h] += __shfl_xor_sync(0xffffffffu, s2[mt][h], 1);
        s1[mt][h] += __shfl_xor_sync(0xffffffffu, s1[mt][h], 2);
        s2[mt][h] += __shfl_xor_sync(0xffffffffu, s2[mt][h], 2);
    }
    if (tig == 0){
#pragma unroll
        for (int mt = 0; mt < 2; mt++)
#pragma unroll
        for (int h = 0; h < 2; h++){
            int row = wm*32 + mt*16 + h*8 + gid;
            scratch[(row*8 + wn)*2 + 0] = s1[mt][h];
            scratch[(row*8 + wn)*2 + 1] = s2[mt][h];
        }
    }
    __syncthreads();
    float mu[2][2], rs[2][2];
#pragma unroll
    for (int mt = 0; mt < 2; mt++)
#pragma unroll
    for (int h = 0; h < 2; h++){
        int row = wm*32 + mt*16 + h*8 + gid;
        float S1 = 0.f, S2 = 0.f;
#pragma unroll
        for (int w = 0; w < 8; w++){
            S1 += scratch[(row*8 + w)*2 + 0];
            S2 += scratch[(row*8 + w)*2 + 1];
        }
        float m_  = S1 * (1.f/256.f);
        float var = S2 * (1.f/256.f) - m_*m_;
        mu[mt][h] = m_;
        rs[mt][h] = rsqrtf(var + 1e-5f);
    }
#pragma unroll
    for (int mt = 0; mt < 2; mt++)
#pragma unroll
    for (int nt = 0; nt < 4; nt++){
        int rA = wm*32 + mt*16 + gid, rB = rA + 8;
        int c  = wn*32 + nt*8 + tig*2;
        float g0 = gP[c],  g1 = gP[c+1];
        float e0 = beP[c], e1 = beP[c+1];
        float vs[4];
        vs[0] = (d[mt][nt][0] + bc[nt][0] - mu[mt][0])*rs[mt][0]*g0 + e0;
        vs[1] = (d[mt][nt][1] + bc[nt][1] - mu[mt][0])*rs[mt][0]*g1 + e1;
        vs[2] = (d[mt][nt][2] + bc[nt][0] - mu[mt][1])*rs[mt][1]*g0 + e0;
        vs[3] = (d[mt][nt][3] + bc[nt][1] - mu[mt][1])*rs[mt][1]*g1 + e1;
#pragma unroll
        for (int j = 0; j < 4; j++)
            vs[j] = 0.5f * vs[j] * (1.f + erff(vs[j] * 0.70710678118654752440f));
        if (ACC){
            gsum[rA*GP + c]     += vs[0];
            gsum[rA*GP + c + 1] += vs[1];
            gsum[rB*GP + c]     += vs[2];
            gsum[rB*GP + c + 1] += vs[3];
        } else {
            gsum[rA*GP + c]     = to_tf32(vs[0]);
            gsum[rA*GP + c + 1] = to_tf32(vs[1]);
            gsum[rB*GP + c]     = to_tf32(vs[2]);
            gsum[rB*GP + c + 1] = to_tf32(vs[3]);
        }
    }
    __syncthreads();
}

// ------------------------------- main kernel -------------------------------

__global__ __launch_bounds__(NTHR, 1)
void fused_main(const float* __restrict__ gf, const float* __restrict__ med,
                const float* __restrict__ sml,
                const float* __restrict__ sm_b1, const float* __restrict__ sm_g,
                const float* __restrict__ sm_be,
                const float* __restrict__ mg_g,  const float* __restrict__ mg_be,
                const float* __restrict__ mg_b2,
                float* __restrict__ out){
    extern __shared__ float smem[];
    float* gsum    = smem;                 // [64][260]
    float* ab0     = gsum + TM*GP;         // [64][36]
    float* ab1     = ab0  + TM*AP;
    float* wb0     = ab1  + TM*AP;         // [256][36]
    float* wb1     = wb0  + 256*WP;
    float* prm     = wb1  + 256*WP;        // 6 x 256
    float* scratch = prm  + 6*256;         // 1024

    const int tid  = threadIdx.x;
    const int lane = tid & 31, wid = tid >> 5;
    const int gid  = lane >> 2, tig = lane & 3;
    const int wm   = wid & 1,  wn  = wid >> 1;     // 2(M) x 8(N) warps
    const int row0 = blockIdx.x * TM;

    if (tid < 256){
        prm[tid]        = sm_b1[tid];
        prm[256 + tid]  = sm_g[tid];
        prm[512 + tid]  = sm_be[tid];
        prm[768 + tid]  = g_bias2[tid];
        prm[1024 + tid] = mg_g[tid];
        prm[1280 + tid] = mg_be[tid];
    }
    for (int i = tid; i < TM*GP; i += NTHR) gsum[i] = 0.f;
    __syncthreads();

    const float4* S4s = (const float4*)sml;
    const float4* S4m = (const float4*)med;
    float d[2][4][4];

    // ---- MLP1 x4: gsum += gelu(LN(pool4(small)@W1 + b1))
#pragma unroll 1
    for (int m = 0; m < 4; m++){
        zero_d(d);
        gemm_pooled(d, S4s, c_adj[m][0], c_adj[m][1], c_adj[m][2], c_adj[m][3],
                    row0, g_W1t, ab0, ab1, wb0, wb1, wm, wn, gid, tig, tid);
        ln_gelu_reg<true>(d, gsum, scratch, prm, prm+256, prm+512, wm, wn, gid, tig);
    }

    // ---- h2 = mean(medium)@W1' + gsum@Cs (+bias2 in LN); g2 -> gsum
    zero_d(d);
    gemm_pooled(d, S4m, 0, 1, 2, 3, row0, g_W1pt,
                ab0, ab1, wb0, wb1, wm, wn, gid, tig, tid);
    gemm_smemA<true>(d, gsum, g_Cs, HID, NC2, wb0, wb1, wm, wn, gid, tig, tid);
    ln_gelu_reg<false>(d, gsum, scratch, prm+768, prm+1024, prm+1280, wm, wn, gid, tig);

    // ---- out = g2 @ W2' + global + mg_b2   (three 256-wide N passes)
#pragma unroll 1
    for (int np = 0; np < 3; np++){
        zero_d(d);
        gemm_smemA<false>(d, gsum, g_W2pt + np*256*HID, HID, NC2,
                          wb0, wb1, wm, wn, gid, tig, tid);
#pragma unroll
        for (int mt = 0; mt < 2; mt++)
#pragma unroll
        for (int nt = 0; nt < 4; nt++){
            int r  = wm*32 + mt*16 + gid;
            int c  = np*256 + wn*32 + nt*8 + tig*2;
            int ro = (row0 + r) * IN_DIM + c;
            float2 bv = *(const float2*)(mg_b2 + c);
            float2 gv = __ldcs((const float2*)(gf + ro));
            __stcs((float2*)(out + ro),
                   make_float2(d[mt][nt][0] + gv.x + bv.x,
                               d[mt][nt][1] + gv.y + bv.y));
            int ro8 = ro + 8*IN_DIM;
            float2 gv2 = __ldcs((const float2*)(gf + ro8));
            __stcs((float2*)(out + ro8),
                   make_float2(d[mt][nt][2] + gv2.x + bv.x,
                               d[mt][nt][3] + gv2.y + bv.y));
        }
    }
}

// ------------------------------- launcher ----------------------------------

extern "C" void kernel_launch(void* const* d_in, const int* in_sizes, int n_in,
                              void* d_out, int out_size){
    const float* gf   = (const float*)d_in[0];
    const float* med  = (const float*)d_in[1];
    const float* sml  = (const float*)d_in[2];
    const float* smw1 = (const float*)d_in[3];
    const float* smb1 = (const float*)d_in[4];
    const float* smg  = (const float*)d_in[5];
    const float* smbe = (const float*)d_in[6];
    const float* smw2 = (const float*)d_in[7];
    const float* smb2 = (const float*)d_in[8];
    const float* mgw1 = (const float*)d_in[9];
    const float* mgb1 = (const float*)d_in[10];
    const float* mgg  = (const float*)d_in[11];
    const float* mgbe = (const float*)d_in[12];
    const float* mgw2 = (const float*)d_in[13];
    const float* mgb2 = (const float*)d_in[14];
    float* out = (float*)d_out;
    (void)in_sizes; (void)n_in; (void)out_size;

    cudaFuncSetAttribute(fused_main, cudaFuncAttributeMaxDynamicSharedMemorySize, SMEM_BYTES);

    prep_transpose<<<IN_DIM, HID>>>(smw1, mgw1, mgw2);
    prep_C<<<HID, HID>>>(smw2, mgw1);
    prep_bias<<<1, HID>>>(smb2, mgw1, mgb1);
    fused_main<<<B_ROWS/TM, NTHR, SMEM_BYTES>>>(gf, med, sml, smb1, smg, smbe,
                                                mgg, mgbe, mgb2, out);
}

// round 11
// speedup vs baseline: 1.2446x; 1.2446x over previous
#include <cuda_runtime.h>
#include <cuda_fp16.h>
#include <cstdint>

// ---------------------------------------------------------------------------
// HierarchicalDownTopFusion — fused fp16 mma.sync (m16n8k16), pipelined (R9).
//
//   g_m   = gelu(LN(pool4(small, adj[m]) @ W1 + b1))           m = 0..3
//   h2    = mean(medium) @ W1' + (Sum_m g_m) @ (0.25*W2@W1') + (b2@W1' + b1')
//   out   = global + gelu(LN(h2)) @ W2' + b2'
//
// R9: fp16 operands (11-bit mantissa == tf32), fp32 accumulate. Halves the
//     mma instruction count, fragment LDS traffic and weight staging vs R6.
//     Structure otherwise identical to R6 (best passing kernel).
// ---------------------------------------------------------------------------

#define B_ROWS 65536
#define IN_DIM 768
#define HID    256
#define TM     64
#define APH    40          // abuf pitch (halves)   -> conflict-free frags
#define WPH    40          // wbuf pitch (halves)
#define GP     260         // gsum pitch (floats)
#define NC1    (IN_DIM/32) // 24
#define NC2    (HID/32)    // 8

// smem floats: gsum 64*260 + 2*abuf(64*40h/2) + 2*wbuf(256*40h/2) + prm + scratch
#define SMEM_FLOATS (TM*GP + 2*(TM*APH/2) + 2*(256*WPH/2) + 6*256 + 512)
#define SMEM_BYTES  (SMEM_FLOATS * 4)   // 125952

__device__ __align__(16) __half g_W1h [HID * IN_DIM];  // sm_w1^T  (fp16)
__device__ __align__(16) __half g_W1ph[HID * IN_DIM];  // mg_w1^T  (fp16)
__device__ __align__(16) __half g_W2ph[IN_DIM * HID];  // mg_w2^T  (fp16)
__device__ __align__(16) __half g_Csh [HID * HID];     // (0.25*sm_w2@mg_w1)^T
__device__ __align__(16) float  g_bias2[HID];          // sm_b2@mg_w1 + mg_b1

// medium order 0,1,3,2: consecutive phases share 2 small slabs (L2 reuse)
__constant__ int c_adj[4][4] = {{0,1,3,4},{1,2,4,5},{4,5,7,8},{3,4,6,7}};

__device__ __forceinline__ void mma16(float* d, const uint32_t* a, uint32_t b0, uint32_t b1){
    asm("mma.sync.aligned.m16n8k16.row.col.f32.f16.f16.f32 "
        "{%0,%1,%2,%3}, {%4,%5,%6,%7}, {%8,%9}, {%0,%1,%2,%3};\n"
        : "+f"(d[0]), "+f"(d[1]), "+f"(d[2]), "+f"(d[3])
        : "r"(a[0]), "r"(a[1]), "r"(a[2]), "r"(a[3]), "r"(b0), "r"(b1));
}

__device__ __forceinline__ uint32_t h2_bits(float x, float y){
    __half2 h = __floats2half2_rn(x, y);
    return *reinterpret_cast<uint32_t*>(&h);
}

__device__ __forceinline__ uint32_t smem_u32(const void* p){
    return (uint32_t)__cvta_generic_to_shared(p);
}
__device__ __forceinline__ void cpa16(uint32_t dst, const void* src){
    asm volatile("cp.async.ca.shared.global [%0], [%1], 16;\n" :: "r"(dst), "l"(src));
}
#define CP_COMMIT asm volatile("cp.async.commit_group;\n")
#define CP_WAIT0  asm volatile("cp.async.wait_group 0;\n")

// ------------------------------- prep kernels ------------------------------

__global__ void prep_transpose(const float* __restrict__ smw1,
                               const float* __restrict__ mgw1,
                               const float* __restrict__ mgw2){
    int k = blockIdx.x;     // 0..767
    int n = threadIdx.x;    // 0..255
    g_W1h [n*IN_DIM + k] = __float2half(smw1[k*HID + n]);
    g_W1ph[n*IN_DIM + k] = __float2half(mgw1[k*HID + n]);
    g_W2ph[k*HID + n]    = __float2half(mgw2[n*IN_DIM + k]);
}

__global__ void prep_C(const float* __restrict__ smw2, const float* __restrict__ mgw1){
    int k = blockIdx.x;     // 0..255
    int n = threadIdx.x;    // 0..255
    float acc = 0.f;
    for (int t = 0; t < IN_DIM; t++)
        acc += smw2[k*IN_DIM + t] * mgw1[t*HID + n];
    g_Csh[n*HID + k] = __float2half(0.25f * acc);
}

__global__ void prep_bias(const float* __restrict__ smb2, const float* __restrict__ mgw1,
                          const float* __restrict__ mgb1){
    int n = threadIdx.x;
    float acc = mgb1[n];
    for (int t = 0; t < IN_DIM; t++)
        acc += smb2[t] * mgw1[t*HID + n];
    g_bias2[n] = acc;
}

// ------------------------------- device helpers ----------------------------

// fp16 A (pitch APH halves) x fp16 W (pitch WPH halves); one K=32 chunk.
__device__ __forceinline__ void mma_chunk_h(float d[2][8][4], const __half* __restrict__ A,
                                            const __half* __restrict__ W,
                                            int wm, int wn, int gid, int tig){
#pragma unroll
    for (int ks = 0; ks < 2; ks++){
        uint32_t a[2][4];
#pragma unroll
        for (int mt = 0; mt < 2; mt++){
            int r = wm*32 + mt*16 + gid;
            int c = ks*16 + tig*2;
            a[mt][0] = *(const uint32_t*)(A + r*APH + c);
            a[mt][1] = *(const uint32_t*)(A + (r+8)*APH + c);
            a[mt][2] = *(const uint32_t*)(A + r*APH + c + 8);
            a[mt][3] = *(const uint32_t*)(A + (r+8)*APH + c + 8);
        }
#pragma unroll
        for (int nt = 0; nt < 8; nt++){
            int n  = wn*64 + nt*8 + gid;
            int kk = ks*16 + tig*2;
            uint32_t b0 = *(const uint32_t*)(W + n*WPH + kk);
            uint32_t b1 = *(const uint32_t*)(W + n*WPH + kk + 8);
            mma16(d[0][nt], a[0], b0, b1);
            mma16(d[1][nt], a[1], b0, b1);
        }
    }
}

// fp32 A from gsum (pitch GP floats, converted to fp16 in-register) x fp16 W.
__device__ __forceinline__ void mma_chunk_g(float d[2][8][4], const float* __restrict__ G,
                                            const __half* __restrict__ W,
                                            int wm, int wn, int gid, int tig){
#pragma unroll
    for (int ks = 0; ks < 2; ks++){
        uint32_t a[2][4];
#pragma unroll
        for (int mt = 0; mt < 2; mt++){
            int r = wm*32 + mt*16 + gid;
            int c = ks*16 + tig*2;
            float2 f0 = *(const float2*)(G + r*GP + c);
            float2 f1 = *(const float2*)(G + (r+8)*GP + c);
            float2 f2 = *(const float2*)(G + r*GP + c + 8);
            float2 f3 = *(const float2*)(G + (r+8)*GP + c + 8);
            a[mt][0] = h2_bits(f0.x, f0.y);
            a[mt][1] = h2_bits(f1.x, f1.y);
            a[mt][2] = h2_bits(f2.x, f2.y);
            a[mt][3] = h2_bits(f3.x, f3.y);
        }
#pragma unroll
        for (int nt = 0; nt < 8; nt++){
            int n  = wn*64 + nt*8 + gid;
            int kk = ks*16 + tig*2;
            uint32_t b0 = *(const uint32_t*)(W + n*WPH + kk);
            uint32_t b1 = *(const uint32_t*)(W + n*WPH + kk + 8);
            mma16(d[0][nt], a[0], b0, b1);
            mma16(d[1][nt], a[1], b0, b1);
        }
    }
}

__device__ __forceinline__ void zero_d(float d[2][8][4]){
#pragma unroll
    for (int mt = 0; mt < 2; mt++)
#pragma unroll
    for (int nt = 0; nt < 8; nt++)
#pragma unroll
    for (int j = 0; j < 4; j++) d[mt][nt][j] = 0.f;
}

// stage one [256 x 32] fp16 weight chunk into wbuf via cp.async
__device__ __forceinline__ void stage_w(__half* wbuf, const __half* __restrict__ Wg,
                                        int rowstride, int kc, int tid){
    uint32_t wb = smem_u32(wbuf);
#pragma unroll
    for (int i = 0; i < 4; i++){
        int idx = i*256 + tid;
        int n = idx >> 2, seg = idx & 3;
        cpa16(wb + (uint32_t)(n*WPH + seg*8)*2u, Wg + n*rowstride + kc*32 + seg*8);
    }
}

// raw fp32 loads for one pooled [64 x 32] A chunk (4 slabs)
struct PoolLd { float4 v[2][4]; };

__device__ __forceinline__ void pool_ld(PoolLd& P, const float4* __restrict__ S4,
                                        int i0,int i1,int i2,int i3,
                                        int row0, int kc, int tid){
    const int SLAB = B_ROWS * (IN_DIM/4);
#pragma unroll
    for (int i = 0; i < 2; i++){
        int idx = i*256 + tid;
        int r = idx >> 3, kk = idx & 7;
        int ro = (row0 + r)*(IN_DIM/4) + kc*8 + kk;
        P.v[i][0] = __ldg(S4 + i0*SLAB + ro);
        P.v[i][1] = __ldg(S4 + i1*SLAB + ro);
        P.v[i][2] = __ldg(S4 + i2*SLAB + ro);
        P.v[i][3] = __ldg(S4 + i3*SLAB + ro);
    }
}

__device__ __forceinline__ void pool_st(const PoolLd& P, __half* abuf, int tid){
    uint2* ab2 = (uint2*)abuf;
#pragma unroll
    for (int i = 0; i < 2; i++){
        int idx = i*256 + tid;
        int r = idx >> 3, kk = idx & 7;
        float mx = 0.25f*(P.v[i][0].x + P.v[i][1].x + P.v[i][2].x + P.v[i][3].x);
        float my = 0.25f*(P.v[i][0].y + P.v[i][1].y + P.v[i][2].y + P.v[i][3].y);
        float mz = 0.25f*(P.v[i][0].z + P.v[i][1].z + P.v[i][2].z + P.v[i][3].z);
        float mw = 0.25f*(P.v[i][0].w + P.v[i][1].w + P.v[i][2].w + P.v[i][3].w);
        uint2 o;
        o.x = h2_bits(mx, my);
        o.y = h2_bits(mz, mw);
        ab2[r*(APH/4) + kk] = o;   // APH/4 = 10 uint2 per row
    }
}

// GEMM over K=768 with pooled A, double-buffered A (reg prefetch) + W (cp.async)
__device__ __forceinline__ void gemm_pooled(float d[2][8][4],
    const float4* __restrict__ S4, int i0,int i1,int i2,int i3, int row0,
    const __half* __restrict__ Wg,
    __half* ab0, __half* ab1, __half* wb0, __half* wb1,
    int wm,int wn,int gid,int tig,int tid)
{
    PoolLd P;
    stage_w(wb0, Wg, IN_DIM, 0, tid);
    CP_COMMIT;
    pool_ld(P, S4, i0,i1,i2,i3, row0, 0, tid);
    pool_st(P, ab0, tid);
    CP_WAIT0;
    __syncthreads();
#pragma unroll 1
    for (int kc = 0; kc < NC1; kc++){
        __half* ac = (kc & 1) ? ab1 : ab0;
        __half* wc = (kc & 1) ? wb1 : wb0;
        if (kc + 1 < NC1){
            __half* wnx = (kc & 1) ? wb0 : wb1;
            stage_w(wnx, Wg, IN_DIM, kc+1, tid);
            CP_COMMIT;
            pool_ld(P, S4, i0,i1,i2,i3, row0, kc+1, tid);
            mma_chunk_h(d, ac, wc, wm, wn, gid, tig);
            __half* anx = (kc & 1) ? ab0 : ab1;
            pool_st(P, anx, tid);
            CP_WAIT0;
        } else {
            mma_chunk_h(d, ac, wc, wm, wn, gid, tig);
        }
        __syncthreads();
    }
}

// GEMM with A resident in smem gsum (fp32, converted at load), W double-buffered
__device__ __forceinline__ void gemm_smemA(float d[2][8][4], const float* Asm,
    const __half* __restrict__ Wg, int rowstride, int nchunks,
    __half* wb0, __half* wb1, int wm,int wn,int gid,int tig,int tid)
{
    stage_w(wb0, Wg, rowstride, 0, tid);
    CP_COMMIT;
    CP_WAIT0;
    __syncthreads();
#pragma unroll 1
    for (int kc = 0; kc < nchunks; kc++){
        __half* wc = (kc & 1) ? wb1 : wb0;
        if (kc + 1 < nchunks){
            __half* wnx = (kc & 1) ? wb0 : wb1;
            stage_w(wnx, Wg, rowstride, kc+1, tid);
            CP_COMMIT;
        }
        mma_chunk_g(d, Asm + kc*32, wc, wm, wn, gid, tig);
        if (kc + 1 < nchunks) CP_WAIT0;
        __syncthreads();
    }
}

// In-register LayerNorm + exact GELU epilogue (identical to R6).
// ACC:  gsum += gelu(LN(d+b))   !ACC: gsum = gelu(LN(d+b))  (fp32; fp16 at load)
template<bool ACC>
__device__ __forceinline__ void ln_gelu_reg(const float d[2][8][4], float* gsum,
        float* scratch,
        const float* bP, const float* gP, const float* beP,
        int wm,int wn,int gid,int tig)
{
    float bc[8][2];
#pragma unroll
    for (int nt = 0; nt < 8; nt++){
        int c = wn*64 + nt*8 + tig*2;
        bc[nt][0] = bP[c]; bc[nt][1] = bP[c+1];
    }
    float s1[2][2] = {{0,0},{0,0}}, s2[2][2] = {{0,0},{0,0}};
#pragma unroll
    for (int mt = 0; mt < 2; mt++)
#pragma unroll
    for (int nt = 0; nt < 8; nt++){
        float v0 = d[mt][nt][0] + bc[nt][0], v1 = d[mt][nt][1] + bc[nt][1];
        float v2 = d[mt][nt][2] + bc[nt][0], v3 = d[mt][nt][3] + bc[nt][1];
        s1[mt][0] += v0 + v1;  s2[mt][0] += v0*v0 + v1*v1;
        s1[mt][1] += v2 + v3;  s2[mt][1] += v2*v2 + v3*v3;
    }
#pragma unroll
    for (int mt = 0; mt < 2; mt++)
#pragma unroll
    for (int h = 0; h < 2; h++){
        s1[mt][h] += __shfl_xor_sync(0xffffffffu, s1[mt][h], 1);
        s2[mt][h] += __shfl_xor_sync(0xffffffffu, s2[mt][h], 1);
        s1[mt][h] += __shfl_xor_sync(0xffffffffu, s1[mt][h], 2);
        s2[mt][h] += __shfl_xor_sync(0xffffffffu, s2[mt][h], 2);
    }
    if (tig == 0){
#pragma unroll
        for (int mt = 0; mt < 2; mt++)
#pragma unroll
        for (int h = 0; h < 2; h++){
            int row = wm*32 + mt*16 + h*8 + gid;
            scratch[(row*4 + wn)*2 + 0] = s1[mt][h];
            scratch[(row*4 + wn)*2 + 1] = s2[mt][h];
        }
    }
    __syncthreads();
    float mu[2][2], rs[2][2];
#pragma unroll
    for (int mt = 0; mt < 2; mt++)
#pragma unroll
    for (int h = 0; h < 2; h++){
        int row = wm*32 + mt*16 + h*8 + gid;
        float S1 = 0.f, S2 = 0.f;
#pragma unroll
        for (int w = 0; w < 4; w++){
            S1 += scratch[(row*4 + w)*2 + 0];
            S2 += scratch[(row*4 + w)*2 + 1];
        }
        float m_  = S1 * (1.f/256.f);
        float var = S2 * (1.f/256.f) - m_*m_;
        mu[mt][h] = m_;
        rs[mt][h] = rsqrtf(var + 1e-5f);
    }
#pragma unroll
    for (int mt = 0; mt < 2; mt++)
#pragma unroll
    for (int nt = 0; nt < 8; nt++){
        int rA = wm*32 + mt*16 + gid, rB = rA + 8;
        int c  = wn*64 + nt*8 + tig*2;
        float g0 = gP[c],  g1 = gP[c+1];
        float e0 = beP[c], e1 = beP[c+1];
        float vs[4];
        vs[0] = (d[mt][nt][0] + bc[nt][0] - mu[mt][0])*rs[mt][0]*g0 + e0;
        vs[1] = (d[mt][nt][1] + bc[nt][1] - mu[mt][0])*rs[mt][0]*g1 + e1;
        vs[2] = (d[mt][nt][2] + bc[nt][0] - mu[mt][1])*rs[mt][1]*g0 + e0;
        vs[3] = (d[mt][nt][3] + bc[nt][1] - mu[mt][1])*rs[mt][1]*g1 + e1;
#pragma unroll
        for (int j = 0; j < 4; j++)
            vs[j] = 0.5f * vs[j] * (1.f + erff(vs[j] * 0.70710678118654752440f));
        if (ACC){
            gsum[rA*GP + c]     += vs[0];
            gsum[rA*GP + c + 1] += vs[1];
            gsum[rB*GP + c]     += vs[2];
            gsum[rB*GP + c + 1] += vs[3];
        } else {
            gsum[rA*GP + c]     = vs[0];
            gsum[rA*GP + c + 1] = vs[1];
            gsum[rB*GP + c]     = vs[2];
            gsum[rB*GP + c + 1] = vs[3];
        }
    }
    __syncthreads();
}

// ------------------------------- main kernel -------------------------------

__global__ __launch_bounds__(256, 1)
void fused_main(const float* __restrict__ gf, const float* __restrict__ med,
                const float* __restrict__ sml,
                const float* __restrict__ sm_b1, const float* __restrict__ sm_g,
                const float* __restrict__ sm_be,
                const float* __restrict__ mg_g,  const float* __restrict__ mg_be,
                const float* __restrict__ mg_b2,
                float* __restrict__ out){
    extern __shared__ float smem[];
    float*  gsum    = smem;                              // [64][260] fp32
    __half* ab0     = (__half*)(gsum + TM*GP);           // [64][40] fp16
    __half* ab1     = ab0 + TM*APH;
    __half* wb0     = ab1 + TM*APH;                      // [256][40] fp16
    __half* wb1     = wb0 + 256*WPH;
    float*  prm     = (float*)(wb1 + 256*WPH);           // 6 x 256
    float*  scratch = prm + 6*256;                       // 512

    const int tid  = threadIdx.x;
    const int lane = tid & 31, wid = tid >> 5;
    const int gid  = lane >> 2, tig = lane & 3;
    const int wm   = wid & 1,  wn  = wid >> 1;           // 2(M) x 4(N) warps
    const int row0 = blockIdx.x * TM;

    prm[tid]        = sm_b1[tid];
    prm[256 + tid]  = sm_g[tid];
    prm[512 + tid]  = sm_be[tid];
    prm[768 + tid]  = g_bias2[tid];
    prm[1024 + tid] = mg_g[tid];
    prm[1280 + tid] = mg_be[tid];
    for (int i = tid; i < TM*GP; i += 256) gsum[i] = 0.f;
    __syncthreads();

    const float4* S4s = (const float4*)sml;
    const float4* S4m = (const float4*)med;
    float d[2][8][4];

    // ---- MLP1 x4: gsum += gelu(LN(pool4(small)@W1 + b1))
#pragma unroll 1
    for (int m = 0; m < 4; m++){
        zero_d(d);
        gemm_pooled(d, S4s, c_adj[m][0], c_adj[m][1], c_adj[m][2], c_adj[m][3],
                    row0, g_W1h, ab0, ab1, wb0, wb1, wm, wn, gid, tig, tid);
        ln_gelu_reg<true>(d, gsum, scratch, prm, prm+256, prm+512, wm, wn, gid, tig);
    }

    // ---- h2 = mean(medium)@W1' + gsum@Cs (+bias2 in LN); g2 -> gsum
    zero_d(d);
    gemm_pooled(d, S4m, 0, 1, 2, 3, row0, g_W1ph,
                ab0, ab1, wb0, wb1, wm, wn, gid, tig, tid);
    gemm_smemA(d, gsum, g_Csh, HID, NC2, wb0, wb1, wm, wn, gid, tig, tid);
    ln_gelu_reg<false>(d, gsum, scratch, prm+768, prm+1024, prm+1280, wm, wn, gid, tig);

    // ---- out = g2 @ W2' + global + mg_b2   (three 256-wide N passes)
#pragma unroll 1
    for (int np = 0; np < 3; np++){
        zero_d(d);
        gemm_smemA(d, gsum, g_W2ph + np*256*HID, HID, NC2,
                   wb0, wb1, wm, wn, gid, tig, tid);
#pragma unroll
        for (int mt = 0; mt < 2; mt++)
#pragma unroll
        for (int nt = 0; nt < 8; nt++){
            int r  = wm*32 + mt*16 + gid;
            int c  = np*256 + wn*64 + nt*8 + tig*2;
            int ro = (row0 + r) * IN_DIM + c;
            float2 bv = *(const float2*)(mg_b2 + c);
            float2 gv = __ldcs((const float2*)(gf + ro));
            __stcs((float2*)(out + ro),
                   make_float2(d[mt][nt][0] + gv.x + bv.x,
                               d[mt][nt][1] + gv.y + bv.y));
            int ro8 = ro + 8*IN_DIM;
            float2 gv2 = __ldcs((const float2*)(gf + ro8));
            __stcs((float2*)(out + ro8),
                   make_float2(d[mt][nt][2] + gv2.x + bv.x,
                               d[mt][nt][3] + gv2.y + bv.y));
        }
    }
}

// ------------------------------- launcher ----------------------------------

extern "C" void kernel_launch(void* const* d_in, const int* in_sizes, int n_in,
                              void* d_out, int out_size){
    const float* gf   = (const float*)d_in[0];
    const float* med  = (const float*)d_in[1];
    const float* sml  = (const float*)d_in[2];
    const float* smw1 = (const float*)d_in[3];
    const float* smb1 = (const float*)d_in[4];
    const float* smg  = (const float*)d_in[5];
    const float* smbe = (const float*)d_in[6];
    const float* smw2 = (const float*)d_in[7];
    const float* smb2 = (const float*)d_in[8];
    const float* mgw1 = (const float*)d_in[9];
    const float* mgb1 = (const float*)d_in[10];
    const float* mgg  = (const float*)d_in[11];
    const float* mgbe = (const float*)d_in[12];
    const float* mgw2 = (const float*)d_in[13];
    const float* mgb2 = (const float*)d_in[14];
    float* out = (float*)d_out;
    (void)in_sizes; (void)n_in; (void)out_size;

    cudaFuncSetAttribute(fused_main, cudaFuncAttributeMaxDynamicSharedMemorySize, SMEM_BYTES);

    prep_transpose<<<IN_DIM, HID>>>(smw1, mgw1, mgw2);
    prep_C<<<HID, HID>>>(smw2, mgw1);
    prep_bias<<<1, HID>>>(smb2, mgw1, mgb1);
    fused_main<<<B_ROWS/TM, 256, SMEM_BYTES>>>(gf, med, sml, smb1, smg, smbe,
                                               mgg, mgbe, mgb2, out);
}

// round 12
// speedup vs baseline: 1.2665x; 1.0176x over previous
#include <cuda_runtime.h>
#include <cuda_fp16.h>
#include <cstdint>

// ---------------------------------------------------------------------------
// HierarchicalDownTopFusion — fused fp16 mma.sync (m16n8k16), pipelined (R10).
//
//   g_m   = gelu(LN(pool4(small, adj[m]) @ W1 + b1))           m = 0..3
//   h2    = mean(medium) @ W1' + (Sum_m g_m) @ (0.25*W2@W1') + (b2@W1' + b1')
//   out   = global + gelu(LN(h2)) @ W2' + b2'
//
// R10 = R9 + (a) distance-2 prefetch.global.L2 on the pooled-A line stream,
//       (b) triple-buffered W staging with distance-2 cp.async groups.
// ---------------------------------------------------------------------------

#define B_ROWS 65536
#define IN_DIM 768
#define HID    256
#define TM     64
#define APH    40          // abuf pitch (halves)
#define WPH    40          // wbuf pitch (halves)
#define GP     260         // gsum pitch (floats)
#define NC1    (IN_DIM/32) // 24
#define NC2    (HID/32)    // 8
#define WBSZ   (256*WPH)   // halves per W buffer

// smem floats: gsum 64*260 + 2*abuf(64*40h/2) + 3*wbuf(256*40h/2) + prm + scratch
#define SMEM_FLOATS (TM*GP + 2*(TM*APH/2) + 3*(256*WPH/2) + 6*256 + 512)
#define SMEM_BYTES  (SMEM_FLOATS * 4)   // 146432

__device__ __align__(16) __half g_W1h [HID * IN_DIM];  // sm_w1^T  (fp16)
__device__ __align__(16) __half g_W1ph[HID * IN_DIM];  // mg_w1^T  (fp16)
__device__ __align__(16) __half g_W2ph[IN_DIM * HID];  // mg_w2^T  (fp16)
__device__ __align__(16) __half g_Csh [HID * HID];     // (0.25*sm_w2@mg_w1)^T
__device__ __align__(16) float  g_bias2[HID];          // sm_b2@mg_w1 + mg_b1

// medium order 0,1,3,2: consecutive phases share 2 small slabs (L2 reuse)
__constant__ int c_adj[4][4] = {{0,1,3,4},{1,2,4,5},{4,5,7,8},{3,4,6,7}};

__device__ __forceinline__ void mma16(float* d, const uint32_t* a, uint32_t b0, uint32_t b1){
    asm("mma.sync.aligned.m16n8k16.row.col.f32.f16.f16.f32 "
        "{%0,%1,%2,%3}, {%4,%5,%6,%7}, {%8,%9}, {%0,%1,%2,%3};\n"
        : "+f"(d[0]), "+f"(d[1]), "+f"(d[2]), "+f"(d[3])
        : "r"(a[0]), "r"(a[1]), "r"(a[2]), "r"(a[3]), "r"(b0), "r"(b1));
}

__device__ __forceinline__ uint32_t h2_bits(float x, float y){
    __half2 h = __floats2half2_rn(x, y);
    return *reinterpret_cast<uint32_t*>(&h);
}

__device__ __forceinline__ uint32_t smem_u32(const void* p){
    return (uint32_t)__cvta_generic_to_shared(p);
}
__device__ __forceinline__ void cpa16(uint32_t dst, const void* src){
    asm volatile("cp.async.ca.shared.global [%0], [%1], 16;\n" :: "r"(dst), "l"(src));
}
__device__ __forceinline__ void l2_prefetch(const void* p){
    asm volatile("prefetch.global.L2 [%0];" :: "l"(p));
}
#define CP_COMMIT asm volatile("cp.async.commit_group;\n")
#define CP_WAIT0  asm volatile("cp.async.wait_group 0;\n")
#define CP_WAIT1  asm volatile("cp.async.wait_group 1;\n")

// ------------------------------- prep kernels ------------------------------

__global__ void prep_transpose(const float* __restrict__ smw1,
                               const float* __restrict__ mgw1,
                               const float* __restrict__ mgw2){
    int k = blockIdx.x;     // 0..767
    int n = threadIdx.x;    // 0..255
    g_W1h [n*IN_DIM + k] = __float2half(smw1[k*HID + n]);
    g_W1ph[n*IN_DIM + k] = __float2half(mgw1[k*HID + n]);
    g_W2ph[k*HID + n]    = __float2half(mgw2[n*IN_DIM + k]);
}

__global__ void prep_C(const float* __restrict__ smw2, const float* __restrict__ mgw1){
    int k = blockIdx.x;     // 0..255
    int n = threadIdx.x;    // 0..255
    float acc = 0.f;
    for (int t = 0; t < IN_DIM; t++)
        acc += smw2[k*IN_DIM + t] * mgw1[t*HID + n];
    g_Csh[n*HID + k] = __float2half(0.25f * acc);
}

__global__ void prep_bias(const float* __restrict__ smb2, const float* __restrict__ mgw1,
                          const float* __restrict__ mgb1){
    int n = threadIdx.x;
    float acc = mgb1[n];
    for (int t = 0; t < IN_DIM; t++)
        acc += smb2[t] * mgw1[t*HID + n];
    g_bias2[n] = acc;
}

// ------------------------------- device helpers ----------------------------

// fp16 A (pitch APH halves) x fp16 W (pitch WPH halves); one K=32 chunk.
__device__ __forceinline__ void mma_chunk_h(float d[2][8][4], const __half* __restrict__ A,
                                            const __half* __restrict__ W,
                                            int wm, int wn, int gid, int tig){
#pragma unroll
    for (int ks = 0; ks < 2; ks++){
        uint32_t a[2][4];
#pragma unroll
        for (int mt = 0; mt < 2; mt++){
            int r = wm*32 + mt*16 + gid;
            int c = ks*16 + tig*2;
            a[mt][0] = *(const uint32_t*)(A + r*APH + c);
            a[mt][1] = *(const uint32_t*)(A + (r+8)*APH + c);
            a[mt][2] = *(const uint32_t*)(A + r*APH + c + 8);
            a[mt][3] = *(const uint32_t*)(A + (r+8)*APH + c + 8);
        }
#pragma unroll
        for (int nt = 0; nt < 8; nt++){
            int n  = wn*64 + nt*8 + gid;
            int kk = ks*16 + tig*2;
            uint32_t b0 = *(const uint32_t*)(W + n*WPH + kk);
            uint32_t b1 = *(const uint32_t*)(W + n*WPH + kk + 8);
            mma16(d[0][nt], a[0], b0, b1);
            mma16(d[1][nt], a[1], b0, b1);
        }
    }
}

// fp32 A from gsum (pitch GP floats, converted to fp16 in-register) x fp16 W.
__device__ __forceinline__ void mma_chunk_g(float d[2][8][4], const float* __restrict__ G,
                                            const __half* __restrict__ W,
                                            int wm, int wn, int gid, int tig){
#pragma unroll
    for (int ks = 0; ks < 2; ks++){
        uint32_t a[2][4];
#pragma unroll
        for (int mt = 0; mt < 2; mt++){
            int r = wm*32 + mt*16 + gid;
            int c = ks*16 + tig*2;
            float2 f0 = *(const float2*)(G + r*GP + c);
            float2 f1 = *(const float2*)(G + (r+8)*GP + c);
            float2 f2 = *(const float2*)(G + r*GP + c + 8);
            float2 f3 = *(const float2*)(G + (r+8)*GP + c + 8);
            a[mt][0] = h2_bits(f0.x, f0.y);
            a[mt][1] = h2_bits(f1.x, f1.y);
            a[mt][2] = h2_bits(f2.x, f2.y);
            a[mt][3] = h2_bits(f3.x, f3.y);
        }
#pragma unroll
        for (int nt = 0; nt < 8; nt++){
            int n  = wn*64 + nt*8 + gid;
            int kk = ks*16 + tig*2;
            uint32_t b0 = *(const uint32_t*)(W + n*WPH + kk);
            uint32_t b1 = *(const uint32_t*)(W + n*WPH + kk + 8);
            mma16(d[0][nt], a[0], b0, b1);
            mma16(d[1][nt], a[1], b0, b1);
        }
    }
}

__device__ __forceinline__ void zero_d(float d[2][8][4]){
#pragma unroll
    for (int mt = 0; mt < 2; mt++)
#pragma unroll
    for (int nt = 0; nt < 8; nt++)
#pragma unroll
    for (int j = 0; j < 4; j++) d[mt][nt][j] = 0.f;
}

// stage one [256 x 32] fp16 weight chunk into a wbuf via cp.async
__device__ __forceinline__ void stage_w(__half* wbuf, const __half* __restrict__ Wg,
                                        int rowstride, int kc, int tid){
    uint32_t wb = smem_u32(wbuf);
#pragma unroll
    for (int i = 0; i < 4; i++){
        int idx = i*256 + tid;
        int n = idx >> 2, seg = idx & 3;
        cpa16(wb + (uint32_t)(n*WPH + seg*8)*2u, Wg + n*rowstride + kc*32 + seg*8);
    }
}

// raw fp32 loads for one pooled [64 x 32] A chunk (4 slabs)
struct PoolLd { float4 v[2][4]; };

__device__ __forceinline__ void pool_ld(PoolLd& P, const float4* __restrict__ S4,
                                        int i0,int i1,int i2,int i3,
                                        int row0, int kc, int tid){
    const int SLAB = B_ROWS * (IN_DIM/4);
#pragma unroll
    for (int i = 0; i < 2; i++){
        int idx = i*256 + tid;
        int r = idx >> 3, kk = idx & 7;
        int ro = (row0 + r)*(IN_DIM/4) + kc*8 + kk;
        P.v[i][0] = __ldg(S4 + i0*SLAB + ro);
        P.v[i][1] = __ldg(S4 + i1*SLAB + ro);
        P.v[i][2] = __ldg(S4 + i2*SLAB + ro);
        P.v[i][3] = __ldg(S4 + i3*SLAB + ro);
    }
}

__device__ __forceinline__ void pool_st(const PoolLd& P, __half* abuf, int tid){
    uint2* ab2 = (uint2*)abuf;
#pragma unroll
    for (int i = 0; i < 2; i++){
        int idx = i*256 + tid;
        int r = idx >> 3, kk = idx & 7;
        float mx = 0.25f*(P.v[i][0].x + P.v[i][1].x + P.v[i][2].x + P.v[i][3].x);
        float my = 0.25f*(P.v[i][0].y + P.v[i][1].y + P.v[i][2].y + P.v[i][3].y);
        float mz = 0.25f*(P.v[i][0].z + P.v[i][1].z + P.v[i][2].z + P.v[i][3].z);
        float mw = 0.25f*(P.v[i][0].w + P.v[i][1].w + P.v[i][2].w + P.v[i][3].w);
        uint2 o;
        o.x = h2_bits(mx, my);
        o.y = h2_bits(mz, mw);
        ab2[r*(APH/4) + kk] = o;
    }
}

// GEMM over K=768 with pooled A: reg-prefetched A + L2 prefetch (dist 2),
// W triple-buffered cp.async (dist 2).
__device__ __forceinline__ void gemm_pooled(float d[2][8][4],
    const float4* __restrict__ S4, int i0,int i1,int i2,int i3, int row0,
    const __half* __restrict__ Wg,
    __half* ab0, __half* ab1, __half* wbB,
    int wm,int wn,int gid,int tig,int tid)
{
    const int SLAB = B_ROWS * (IN_DIM/4);
    // per-thread prefetch line: slab = tid>>6, row = tid&63 (256 lines/chunk)
    int sp = tid >> 6;
    int ips = (sp == 0) ? i0 : (sp == 1) ? i1 : (sp == 2) ? i2 : i3;
    const float4* pref = S4 + (size_t)ips*SLAB + (size_t)(row0 + (tid & 63))*(IN_DIM/4);

    PoolLd P;
    stage_w(wbB,        Wg, IN_DIM, 0, tid); CP_COMMIT;
    stage_w(wbB + WBSZ, Wg, IN_DIM, 1, tid); CP_COMMIT;
    pool_ld(P, S4, i0,i1,i2,i3, row0, 0, tid);
    pool_st(P, ab0, tid);
    l2_prefetch(pref + 1*8);
    l2_prefetch(pref + 2*8);
    CP_WAIT1;              // W0 ready (W1 in flight)
    __syncthreads();
#pragma unroll 1
    for (int kc = 0; kc < NC1; kc++){
        __half* wc = wbB + (kc % 3)*WBSZ;
        if (kc + 2 < NC1){
            stage_w(wbB + ((kc + 2) % 3)*WBSZ, Wg, IN_DIM, kc + 2, tid);
            CP_COMMIT;
        }
        if (kc + 1 < NC1){
            pool_ld(P, S4, i0,i1,i2,i3, row0, kc+1, tid);
            if (kc + 3 < NC1) l2_prefetch(pref + (kc + 3)*8);
            mma_chunk_h(d, (kc & 1) ? ab1 : ab0, wc, wm, wn, gid, tig);
            pool_st(P, (kc & 1) ? ab0 : ab1, tid);
        } else {
            mma_chunk_h(d, (kc & 1) ? ab1 : ab0, wc, wm, wn, gid, tig);
        }
        if (kc + 2 < NC1) CP_WAIT1; else CP_WAIT0;
        __syncthreads();
    }
}

// GEMM with A resident in smem gsum (fp32, converted at load); W 3-buf dist-2.
__device__ __forceinline__ void gemm_smemA(float d[2][8][4], const float* Asm,
    const __half* __restrict__ Wg, int rowstride, int nchunks,
    __half* wbB, int wm,int wn,int gid,int tig,int tid)
{
    stage_w(wbB,        Wg, rowstride, 0, tid); CP_COMMIT;
    stage_w(wbB + WBSZ, Wg, rowstride, 1, tid); CP_COMMIT;
    CP_WAIT1;
    __syncthreads();
#pragma unroll 1
    for (int kc = 0; kc < nchunks; kc++){
        __half* wc = wbB + (kc % 3)*WBSZ;
        if (kc + 2 < nchunks){
            stage_w(wbB + ((kc + 2) % 3)*WBSZ, Wg, rowstride, kc + 2, tid);
            CP_COMMIT;
        }
        mma_chunk_g(d, Asm + kc*32, wc, wm, wn, gid, tig);
        if (kc + 2 < nchunks) CP_WAIT1; else CP_WAIT0;
        __syncthreads();
    }
}

// In-register LayerNorm + exact GELU epilogue (identical to R9).
template<bool ACC>
__device__ __forceinline__ void ln_gelu_reg(const float d[2][8][4], float* gsum,
        float* scratch,
        const float* bP, const float* gP, const float* beP,
        int wm,int wn,int gid,int tig)
{
    float bc[8][2];
#pragma unroll
    for (int nt = 0; nt < 8; nt++){
        int c = wn*64 + nt*8 + tig*2;
        bc[nt][0] = bP[c]; bc[nt][1] = bP[c+1];
    }
    float s1[2][2] = {{0,0},{0,0}}, s2[2][2] = {{0,0},{0,0}};
#pragma unroll
    for (int mt = 0; mt < 2; mt++)
#pragma unroll
    for (int nt = 0; nt < 8; nt++){
        float v0 = d[mt][nt][0] + bc[nt][0], v1 = d[mt][nt][1] + bc[nt][1];
        float v2 = d[mt][nt][2] + bc[nt][0], v3 = d[mt][nt][3] + bc[nt][1];
        s1[mt][0] += v0 + v1;  s2[mt][0] += v0*v0 + v1*v1;
        s1[mt][1] += v2 + v3;  s2[mt][1] += v2*v2 + v3*v3;
    }
#pragma unroll
    for (int mt = 0; mt < 2; mt++)
#pragma unroll
    for (int h = 0; h < 2; h++){
        s1[mt][h] += __shfl_xor_sync(0xffffffffu, s1[mt][h], 1);
        s2[mt][h] += __shfl_xor_sync(0xffffffffu, s2[mt][h], 1);
        s1[mt][h] += __shfl_xor_sync(0xffffffffu, s1[mt][h], 2);
        s2[mt][h] += __shfl_xor_sync(0xffffffffu, s2[mt][h], 2);
    }
    if (tig == 0){
#pragma unroll
        for (int mt = 0; mt < 2; mt++)
#pragma unroll
        for (int h = 0; h < 2; h++){
            int row = wm*32 + mt*16 + h*8 + gid;
            scratch[(row*4 + wn)*2 + 0] = s1[mt][h];
            scratch[(row*4 + wn)*2 + 1] = s2[mt][h];
        }
    }
    __syncthreads();
    float mu[2][2], rs[2][2];
#pragma unroll
    for (int mt = 0; mt < 2; mt++)
#pragma unroll
    for (int h = 0; h < 2; h++){
        int row = wm*32 + mt*16 + h*8 + gid;
        float S1 = 0.f, S2 = 0.f;
#pragma unroll
        for (int w = 0; w < 4; w++){
            S1 += scratch[(row*4 + w)*2 + 0];
            S2 += scratch[(row*4 + w)*2 + 1];
        }
        float m_  = S1 * (1.f/256.f);
        float var = S2 * (1.f/256.f) - m_*m_;
        mu[mt][h] = m_;
        rs[mt][h] = rsqrtf(var + 1e-5f);
    }
#pragma unroll
    for (int mt = 0; mt < 2; mt++)
#pragma unroll
    for (int nt = 0; nt < 8; nt++){
        int rA = wm*32 + mt*16 + gid, rB = rA + 8;
        int c  = wn*64 + nt*8 + tig*2;
        float g0 = gP[c],  g1 = gP[c+1];
        float e0 = beP[c], e1 = beP[c+1];
        float vs[4];
        vs[0] = (d[mt][nt][0] + bc[nt][0] - mu[mt][0])*rs[mt][0]*g0 + e0;
        vs[1] = (d[mt][nt][1] + bc[nt][1] - mu[mt][0])*rs[mt][0]*g1 + e1;
        vs[2] = (d[mt][nt][2] + bc[nt][0] - mu[mt][1])*rs[mt][1]*g0 + e0;
        vs[3] = (d[mt][nt][3] + bc[nt][1] - mu[mt][1])*rs[mt][1]*g1 + e1;
#pragma unroll
        for (int j = 0; j < 4; j++)
            vs[j] = 0.5f * vs[j] * (1.f + erff(vs[j] * 0.70710678118654752440f));
        if (ACC){
            gsum[rA*GP + c]     += vs[0];
            gsum[rA*GP + c + 1] += vs[1];
            gsum[rB*GP + c]     += vs[2];
            gsum[rB*GP + c + 1] += vs[3];
        } else {
            gsum[rA*GP + c]     = vs[0];
            gsum[rA*GP + c + 1] = vs[1];
            gsum[rB*GP + c]     = vs[2];
            gsum[rB*GP + c + 1] = vs[3];
        }
    }
    __syncthreads();
}

// ------------------------------- main kernel -------------------------------

__global__ __launch_bounds__(256, 1)
void fused_main(const float* __restrict__ gf, const float* __restrict__ med,
                const float* __restrict__ sml,
                const float* __restrict__ sm_b1, const float* __restrict__ sm_g,
                const float* __restrict__ sm_be,
                const float* __restrict__ mg_g,  const float* __restrict__ mg_be,
                const float* __restrict__ mg_b2,
                float* __restrict__ out){
    extern __shared__ float smem[];
    float*  gsum    = smem;                              // [64][260] fp32
    __half* ab0     = (__half*)(gsum + TM*GP);           // [64][40] fp16
    __half* ab1     = ab0 + TM*APH;
    __half* wbB     = ab1 + TM*APH;                      // 3 x [256][40] fp16
    float*  prm     = (float*)(wbB + 3*WBSZ);            // 6 x 256
    float*  scratch = prm + 6*256;                       // 512

    const int tid  = threadIdx.x;
    const int lane = tid & 31, wid = tid >> 5;
    const int gid  = lane >> 2, tig = lane & 3;
    const int wm   = wid & 1,  wn  = wid >> 1;           // 2(M) x 4(N) warps
    const int row0 = blockIdx.x * TM;

    prm[tid]        = sm_b1[tid];
    prm[256 + tid]  = sm_g[tid];
    prm[512 + tid]  = sm_be[tid];
    prm[768 + tid]  = g_bias2[tid];
    prm[1024 + tid] = mg_g[tid];
    prm[1280 + tid] = mg_be[tid];
    for (int i = tid; i < TM*GP; i += 256) gsum[i] = 0.f;
    __syncthreads();

    const float4* S4s = (const float4*)sml;
    const float4* S4m = (const float4*)med;
    float d[2][8][4];

    // ---- MLP1 x4: gsum += gelu(LN(pool4(small)@W1 + b1))
#pragma unroll 1
    for (int m = 0; m < 4; m++){
        zero_d(d);
        gemm_pooled(d, S4s, c_adj[m][0], c_adj[m][1], c_adj[m][2], c_adj[m][3],
                    row0, g_W1h, ab0, ab1, wbB, wm, wn, gid, tig, tid);
        ln_gelu_reg<true>(d, gsum, scratch, prm, prm+256, prm+512, wm, wn, gid, tig);
    }

    // ---- h2 = mean(medium)@W1' + gsum@Cs (+bias2 in LN); g2 -> gsum
    zero_d(d);
    gemm_pooled(d, S4m, 0, 1, 2, 3, row0, g_W1ph,
                ab0, ab1, wbB, wm, wn, gid, tig, tid);
    gemm_smemA(d, gsum, g_Csh, HID, NC2, wbB, wm, wn, gid, tig, tid);
    ln_gelu_reg<false>(d, gsum, scratch, prm+768, prm+1024, prm+1280, wm, wn, gid, tig);

    // ---- out = g2 @ W2' + global + mg_b2   (three 256-wide N passes)
#pragma unroll 1
    for (int np = 0; np < 3; np++){
        zero_d(d);
        gemm_smemA(d, gsum, g_W2ph + np*256*HID, HID, NC2,
                   wbB, wm, wn, gid, tig, tid);
#pragma unroll
        for (int mt = 0; mt < 2; mt++)
#pragma unroll
        for (int nt = 0; nt < 8; nt++){
            int r  = wm*32 + mt*16 + gid;
            int c  = np*256 + wn*64 + nt*8 + tig*2;
            int ro = (row0 + r) * IN_DIM + c;
            float2 bv = *(const float2*)(mg_b2 + c);
            float2 gv = __ldcs((const float2*)(gf + ro));
            __stcs((float2*)(out + ro),
                   make_float2(d[mt][nt][0] + gv.x + bv.x,
                               d[mt][nt][1] + gv.y + bv.y));
            int ro8 = ro + 8*IN_DIM;
            float2 gv2 = __ldcs((const float2*)(gf + ro8));
            __stcs((float2*)(out + ro8),
                   make_float2(d[mt][nt][2] + gv2.x + bv.x,
                               d[mt][nt][3] + gv2.y + bv.y));
        }
    }
}

// ------------------------------- launcher ----------------------------------

extern "C" void kernel_launch(void* const* d_in, const int* in_sizes, int n_in,
                              void* d_out, int out_size){
    const float* gf   = (const float*)d_in[0];
    const float* med  = (const float*)d_in[1];
    const float* sml  = (const float*)d_in[2];
    const float* smw1 = (const float*)d_in[3];
    const float* smb1 = (const float*)d_in[4];
    const float* smg  = (const float*)d_in[5];
    const float* smbe = (const float*)d_in[6];
    const float* smw2 = (const float*)d_in[7];
    const float* smb2 = (const float*)d_in[8];
    const float* mgw1 = (const float*)d_in[9];
    const float* mgb1 = (const float*)d_in[10];
    const float* mgg  = (const float*)d_in[11];
    const float* mgbe = (const float*)d_in[12];
    const float* mgw2 = (const float*)d_in[13];
    const float* mgb2 = (const float*)d_in[14];
    float* out = (float*)d_out;
    (void)in_sizes; (void)n_in; (void)out_size;

    cudaFuncSetAttribute(fused_main, cudaFuncAttributeMaxDynamicSharedMemorySize, SMEM_BYTES);

    prep_transpose<<<IN_DIM, HID>>>(smw1, mgw1, mgw2);
    prep_C<<<HID, HID>>>(smw2, mgw1);
    prep_bias<<<1, HID>>>(smb2, mgw1, mgb1);
    fused_main<<<B_ROWS/TM, 256, SMEM_BYTES>>>(gf, med, sml, smb1, smg, smbe,
                                               mgg, mgbe, mgb2, out);
}

// round 14
// speedup vs baseline: 1.3334x; 1.0528x over previous
#include <cuda_runtime.h>
#include <cuda_fp16.h>
#include <cstdint>

// ---------------------------------------------------------------------------
// HierarchicalDownTopFusion — fused fp16 mma.sync (m16n8k16), pipelined (R11).
//
//   g_m   = gelu(LN(pool4(small, adj[m]) @ W1 + b1))           m = 0..3
//   h2    = mean(medium) @ W1' + (Sum_m g_m) @ (0.25*W2@W1') + (b2@W1' + b1')
//   out   = global + gelu(LN(h2)) @ W2' + b2'
//
// R11 = R10 with K-chunk doubled to 64: half the loop iterations / barriers,
//       2x mma work per barrier. Pooled-A loads split into two batches
//       interleaved with the two mma half-chunks (register cap ~32 floats).
// ---------------------------------------------------------------------------

#define B_ROWS 65536
#define IN_DIM 768
#define HID    256
#define TM     64
#define APH    72          // abuf pitch (halves) — 144B rows, conflict-free
#define WPH    72          // wbuf pitch (halves)
#define GP     260         // gsum pitch (floats)
#define NCH1   (IN_DIM/64) // 12
#define NCH2   (HID/64)    // 4
#define WBSZ   (256*WPH)   // halves per W buffer

// smem floats: gsum 64*260 + 2*abuf(64*72h/2) + 2*wbuf(256*72h/2) + prm + scratch
#define SMEM_FLOATS (TM*GP + 2*(TM*APH/2) + 2*(256*WPH/2) + 6*256 + 512)
#define SMEM_BYTES  (SMEM_FLOATS * 4)   // 166912

__device__ __align__(16) __half g_W1h [HID * IN_DIM];  // sm_w1^T  (fp16)
__device__ __align__(16) __half g_W1ph[HID * IN_DIM];  // mg_w1^T  (fp16)
__device__ __align__(16) __half g_W2ph[IN_DIM * HID];  // mg_w2^T  (fp16)
__device__ __align__(16) __half g_Csh [HID * HID];     // (0.25*sm_w2@mg_w1)^T
__device__ __align__(16) float  g_bias2[HID];          // sm_b2@mg_w1 + mg_b1

// medium order 0,1,3,2: consecutive phases share 2 small slabs (L2 reuse)
__constant__ int c_adj[4][4] = {{0,1,3,4},{1,2,4,5},{4,5,7,8},{3,4,6,7}};

__device__ __forceinline__ void mma16(float* d, const uint32_t* a, uint32_t b0, uint32_t b1){
    asm("mma.sync.aligned.m16n8k16.row.col.f32.f16.f16.f32 "
        "{%0,%1,%2,%3}, {%4,%5,%6,%7}, {%8,%9}, {%0,%1,%2,%3};\n"
        : "+f"(d[0]), "+f"(d[1]), "+f"(d[2]), "+f"(d[3])
        : "r"(a[0]), "r"(a[1]), "r"(a[2]), "r"(a[3]), "r"(b0), "r"(b1));
}

__device__ __forceinline__ uint32_t h2_bits(float x, float y){
    __half2 h = __floats2half2_rn(x, y);
    return *reinterpret_cast<uint32_t*>(&h);
}

__device__ __forceinline__ uint32_t smem_u32(const void* p){
    return (uint32_t)__cvta_generic_to_shared(p);
}
__device__ __forceinline__ void cpa16(uint32_t dst, const void* src){
    asm volatile("cp.async.ca.shared.global [%0], [%1], 16;\n" :: "r"(dst), "l"(src));
}
__device__ __forceinline__ void l2_prefetch(const void* p){
    asm volatile("prefetch.global.L2 [%0];" :: "l"(p));
}
#define CP_COMMIT asm volatile("cp.async.commit_group;\n")
#define CP_WAIT0  asm volatile("cp.async.wait_group 0;\n")

// ------------------------------- prep kernels ------------------------------

__global__ void prep_transpose(const float* __restrict__ smw1,
                               const float* __restrict__ mgw1,
                               const float* __restrict__ mgw2){
    int k = blockIdx.x;     // 0..767
    int n = threadIdx.x;    // 0..255
    g_W1h [n*IN_DIM + k] = __float2half(smw1[k*HID + n]);
    g_W1ph[n*IN_DIM + k] = __float2half(mgw1[k*HID + n]);
    g_W2ph[k*HID + n]    = __float2half(mgw2[n*IN_DIM + k]);
}

__global__ void prep_C(const float* __restrict__ smw2, const float* __restrict__ mgw1){
    int k = blockIdx.x;     // 0..255
    int n = threadIdx.x;    // 0..255
    float acc = 0.f;
    for (int t = 0; t < IN_DIM; t++)
        acc += smw2[k*IN_DIM + t] * mgw1[t*HID + n];
    g_Csh[n*HID + k] = __float2half(0.25f * acc);
}

__global__ void prep_bias(const float* __restrict__ smb2, const float* __restrict__ mgw1,
                          const float* __restrict__ mgb1){
    int n = threadIdx.x;
    float acc = mgb1[n];
    for (int t = 0; t < IN_DIM; t++)
        acc += smb2[t] * mgw1[t*HID + n];
    g_bias2[n] = acc;
}

// ------------------------------- device helpers ----------------------------

// half of a K=64 chunk (two K=16 mma steps), fp16 A in smem.
template<int KS0>
__device__ __forceinline__ void mma_half_h(float d[2][8][4], const __half* __restrict__ A,
                                           const __half* __restrict__ W,
                                           int wm, int wn, int gid, int tig){
#pragma unroll
    for (int ks = KS0; ks < KS0 + 2; ks++){
        uint32_t a[2][4];
#pragma unroll
        for (int mt = 0; mt < 2; mt++){
            int r = wm*32 + mt*16 + gid;
            int c = ks*16 + tig*2;
            a[mt][0] = *(const uint32_t*)(A + r*APH + c);
            a[mt][1] = *(const uint32_t*)(A + (r+8)*APH + c);
            a[mt][2] = *(const uint32_t*)(A + r*APH + c + 8);
            a[mt][3] = *(const uint32_t*)(A + (r+8)*APH + c + 8);
        }
#pragma unroll
        for (int nt = 0; nt < 8; nt++){
            int n  = wn*64 + nt*8 + gid;
            int kk = ks*16 + tig*2;
            uint32_t b0 = *(const uint32_t*)(W + n*WPH + kk);
            uint32_t b1 = *(const uint32_t*)(W + n*WPH + kk + 8);
            mma16(d[0][nt], a[0], b0, b1);
            mma16(d[1][nt], a[1], b0, b1);
        }
    }
}

// full K=64 chunk from fp32 gsum (converted to fp16 at load), fp16 W in smem.
__device__ __forceinline__ void mma_chunk_g(float d[2][8][4], const float* __restrict__ G,
                                            const __half* __restrict__ W,
                                            int wm, int wn, int gid, int tig){
#pragma unroll
    for (int ks = 0; ks < 4; ks++){
        uint32_t a[2][4];
#pragma unroll
        for (int mt = 0; mt < 2; mt++){
            int r = wm*32 + mt*16 + gid;
            int c = ks*16 + tig*2;
            float2 f0 = *(const float2*)(G + r*GP + c);
            float2 f1 = *(const float2*)(G + (r+8)*GP + c);
            float2 f2 = *(const float2*)(G + r*GP + c + 8);
            float2 f3 = *(const float2*)(G + (r+8)*GP + c + 8);
            a[mt][0] = h2_bits(f0.x, f0.y);
            a[mt][1] = h2_bits(f1.x, f1.y);
            a[mt][2] = h2_bits(f2.x, f2.y);
            a[mt][3] = h2_bits(f3.x, f3.y);
        }
#pragma unroll
        for (int nt = 0; nt < 8; nt++){
            int n  = wn*64 + nt*8 + gid;
            int kk = ks*16 + tig*2;
            uint32_t b0 = *(const uint32_t*)(W + n*WPH + kk);
            uint32_t b1 = *(const uint32_t*)(W + n*WPH + kk + 8);
            mma16(d[0][nt], a[0], b0, b1);
            mma16(d[1][nt], a[1], b0, b1);
        }
    }
}

__device__ __forceinline__ void zero_d(float d[2][8][4]){
#pragma unroll
    for (int mt = 0; mt < 2; mt++)
#pragma unroll
    for (int nt = 0; nt < 8; nt++)
#pragma unroll
    for (int j = 0; j < 4; j++) d[mt][nt][j] = 0.f;
}

// stage one [256 x 64] fp16 weight chunk into a wbuf via cp.async (8 x 16B/thr)
__device__ __forceinline__ void stage_w(__half* wbuf, const __half* __restrict__ Wg,
                                        int rowstride, int kc, int tid){
    uint32_t wb = smem_u32(wbuf);
#pragma unroll
    for (int i = 0; i < 8; i++){
        int idx = i*256 + tid;
        int n = idx >> 3, seg = idx & 7;
        cpa16(wb + (uint32_t)(n*WPH + seg*8)*2u, Wg + n*rowstride + kc*64 + seg*8);
    }
}

// raw fp32 loads for one pooled [64 x 32] A sub-chunk (4 slabs)
struct PoolLd { float4 v[2][4]; };

// sc = global 32-col sub-chunk index (0..23)
__device__ __forceinline__ void pool_ld(PoolLd& P, const float4* __restrict__ S4,
                                        int i0,int i1,int i2,int i3,
                                        int row0, int sc, int tid){
    const int SLAB = B_ROWS * (IN_DIM/4);
#pragma unroll
    for (int i = 0; i < 2; i++){
        int idx = i*256 + tid;
        int r = idx >> 3, kk = idx & 7;
        int ro = (row0 + r)*(IN_DIM/4) + sc*8 + kk;
        P.v[i][0] = __ldg(S4 + i0*SLAB + ro);
        P.v[i][1] = __ldg(S4 + i1*SLAB + ro);
        P.v[i][2] = __ldg(S4 + i2*SLAB + ro);
        P.v[i][3] = __ldg(S4 + i3*SLAB + ro);
    }
}

// cs = 0/1: which 32-col half of the 64-col abuf row to write
__device__ __forceinline__ void pool_st(const PoolLd& P, __half* abuf, int cs, int tid){
    uint2* ab2 = (uint2*)abuf;
#pragma unroll
    for (int i = 0; i < 2; i++){
        int idx = i*256 + tid;
        int r = idx >> 3, kk = idx & 7;
        float mx = 0.25f*(P.v[i][0].x + P.v[i][1].x + P.v[i][2].x + P.v[i][3].x);
        float my = 0.25f*(P.v[i][0].y + P.v[i][1].y + P.v[i][2].y + P.v[i][3].y);
        float mz = 0.25f*(P.v[i][0].z + P.v[i][1].z + P.v[i][2].z + P.v[i][3].z);
        float mw = 0.25f*(P.v[i][0].w + P.v[i][1].w + P.v[i][2].w + P.v[i][3].w);
        uint2 o;
        o.x = h2_bits(mx, my);
        o.y = h2_bits(mz, mw);
        ab2[r*(APH/4) + cs*8 + kk] = o;   // APH/4 = 18 uint2 per row
    }
}

// GEMM over K=768 with pooled A (K-chunk 64): A loads interleaved between the
// two mma half-chunks; W double-buffered cp.async (full-chunk lead);
// L2 prefetch one chunk ahead of the A load stream.
__device__ __forceinline__ void gemm_pooled(float d[2][8][4],
    const float4* __restrict__ S4, int i0,int i1,int i2,int i3, int row0,
    const __half* __restrict__ Wg,
    __half* ab0, __half* ab1, __half* wb0, __half* wb1,
    int wm,int wn,int gid,int tig,int tid)
{
    const int SLAB = B_ROWS * (IN_DIM/4);
    // per-thread prefetch: slab = tid>>6, row = tid&63; 2 x 128B lines / chunk
    int sp = tid >> 6;
    int ips = (sp == 0) ? i0 : (sp == 1) ? i1 : (sp == 2) ? i2 : i3;
    const float4* pref = S4 + (size_t)ips*SLAB + (size_t)(row0 + (tid & 63))*(IN_DIM/4);

    PoolLd P;
    stage_w(wb0, Wg, IN_DIM, 0, tid);
    CP_COMMIT;
    pool_ld(P, S4, i0,i1,i2,i3, row0, 0, tid);
    pool_st(P, ab0, 0, tid);
    pool_ld(P, S4, i0,i1,i2,i3, row0, 1, tid);
    pool_st(P, ab0, 1, tid);
    l2_prefetch(pref + 16);            // chunk 1, first line
    l2_prefetch(pref + 24);            // chunk 1, second line
    CP_WAIT0;
    __syncthreads();
#pragma unroll 1
    for (int kc = 0; kc < NCH1; kc++){
        const __half* ac = (kc & 1) ? ab1 : ab0;
        const __half* wc = (kc & 1) ? wb1 : wb0;
        if (kc + 1 < NCH1){
            __half* wnx = (kc & 1) ? wb0 : wb1;
            __half* anx = (kc & 1) ? ab0 : ab1;
            stage_w(wnx, Wg, IN_DIM, kc + 1, tid);
            CP_COMMIT;
            pool_ld(P, S4, i0,i1,i2,i3, row0, 2*(kc+1), tid);
            if (kc + 2 < NCH1){
                l2_prefetch(pref + (kc + 2)*16);
                l2_prefetch(pref + (kc + 2)*16 + 8);
            }
            mma_half_h<0>(d, ac, wc, wm, wn, gid, tig);
            pool_st(P, anx, 0, tid);
            pool_ld(P, S4, i0,i1,i2,i3, row0, 2*(kc+1) + 1, tid);
            mma_half_h<2>(d, ac, wc, wm, wn, gid, tig);
            pool_st(P, anx, 1, tid);
            CP_WAIT0;
        } else {
            mma_half_h<0>(d, ac, wc, wm, wn, gid, tig);
            mma_half_h<2>(d, ac, wc, wm, wn, gid, tig);
        }
        __syncthreads();
    }
}

// GEMM with A resident in smem gsum (fp32, converted at load); W 2-buf dist-1.
__device__ __forceinline__ void gemm_smemA(float d[2][8][4], const float* Asm,
    const __half* __restrict__ Wg, int rowstride, int nchunks,
    __half* wb0, __half* wb1, int wm,int wn,int gid,int tig,int tid)
{
    stage_w(wb0, Wg, rowstride, 0, tid);
    CP_COMMIT;
    CP_WAIT0;
    __syncthreads();
#pragma unroll 1
    for (int kc = 0; kc < nchunks; kc++){
        const __half* wc = (kc & 1) ? wb1 : wb0;
        if (kc + 1 < nchunks){
            __half* wnx = (kc & 1) ? wb0 : wb1;
            stage_w(wnx, Wg, rowstride, kc + 1, tid);
            CP_COMMIT;
        }
        mma_chunk_g(d, Asm + kc*64, wc, wm, wn, gid, tig);
        if (kc + 1 < nchunks) CP_WAIT0;
        __syncthreads();
    }
}

// In-register LayerNorm + exact GELU epilogue (identical to R9/R10).
template<bool ACC>
__device__ __forceinline__ void ln_gelu_reg(const float d[2][8][4], float* gsum,
        float* scratch,
        const float* bP, const float* gP, const float* beP,
        int wm,int wn,int gid,int tig)
{
    float bc[8][2];
#pragma unroll
    for (int nt = 0; nt < 8; nt++){
        int c = wn*64 + nt*8 + tig*2;
        bc[nt][0] = bP[c]; bc[nt][1] = bP[c+1];
    }
    float s1[2][2] = {{0,0},{0,0}}, s2[2][2] = {{0,0},{0,0}};
#pragma unroll
    for (int mt = 0; mt < 2; mt++)
#pragma unroll
    for (int nt = 0; nt < 8; nt++){
        float v0 = d[mt][nt][0] + bc[nt][0], v1 = d[mt][nt][1] + bc[nt][1];
        float v2 = d[mt][nt][2] + bc[nt][0], v3 = d[mt][nt][3] + bc[nt][1];
        s1[mt][0] += v0 + v1;  s2[mt][0] += v0*v0 + v1*v1;
        s1[mt][1] += v2 + v3;  s2[mt][1] += v2*v2 + v3*v3;
    }
#pragma unroll
    for (int mt = 0; mt < 2; mt++)
#pragma unroll
    for (int h = 0; h < 2; h++){
        s1[mt][h] += __shfl_xor_sync(0xffffffffu, s1[mt][h], 1);
        s2[mt][h] += __shfl_xor_sync(0xffffffffu, s2[mt][h], 1);
        s1[mt][h] += __shfl_xor_sync(0xffffffffu, s1[mt][h], 2);
        s2[mt][h] += __shfl_xor_sync(0xffffffffu, s2[mt][h], 2);
    }
    if (tig == 0){
#pragma unroll
        for (int mt = 0; mt < 2; mt++)
#pragma unroll
        for (int h = 0; h < 2; h++){
            int row = wm*32 + mt*16 + h*8 + gid;
            scratch[(row*4 + wn)*2 + 0] = s1[mt][h];
            scratch[(row*4 + wn)*2 + 1] = s2[mt][h];
        }
    }
    __syncthreads();
    float mu[2][2], rs[2][2];
#pragma unroll
    for (int mt = 0; mt < 2; mt++)
#pragma unroll
    for (int h = 0; h < 2; h++){
        int row = wm*32 + mt*16 + h*8 + gid;
        float S1 = 0.f, S2 = 0.f;
#pragma unroll
        for (int w = 0; w < 4; w++){
            S1 += scratch[(row*4 + w)*2 + 0];
            S2 += scratch[(row*4 + w)*2 + 1];
        }
        float m_  = S1 * (1.f/256.f);
        float var = S2 * (1.f/256.f) - m_*m_;
        mu[mt][h] = m_;
        rs[mt][h] = rsqrtf(var + 1e-5f);
    }
#pragma unroll
    for (int mt = 0; mt < 2; mt++)
#pragma unroll
    for (int nt = 0; nt < 8; nt++){
        int rA = wm*32 + mt*16 + gid, rB = rA + 8;
        int c  = wn*64 + nt*8 + tig*2;
        float g0 = gP[c],  g1 = gP[c+1];
        float e0 = beP[c], e1 = beP[c+1];
        float vs[4];
        vs[0] = (d[mt][nt][0] + bc[nt][0] - mu[mt][0])*rs[mt][0]*g0 + e0;
        vs[1] = (d[mt][nt][1] + bc[nt][1] - mu[mt][0])*rs[mt][0]*g1 + e1;
        vs[2] = (d[mt][nt][2] + bc[nt][0] - mu[mt][1])*rs[mt][1]*g0 + e0;
        vs[3] = (d[mt][nt][3] + bc[nt][1] - mu[mt][1])*rs[mt][1]*g1 + e1;
#pragma unroll
        for (int j = 0; j < 4; j++)
            vs[j] = 0.5f * vs[j] * (1.f + erff(vs[j] * 0.70710678118654752440f));
        if (ACC){
            gsum[rA*GP + c]     += vs[0];
            gsum[rA*GP + c + 1] += vs[1];
            gsum[rB*GP + c]     += vs[2];
            gsum[rB*GP + c + 1] += vs[3];
        } else {
            gsum[rA*GP + c]     = vs[0];
            gsum[rA*GP + c + 1] = vs[1];
            gsum[rB*GP + c]     = vs[2];
            gsum[rB*GP + c + 1] = vs[3];
        }
    }
    __syncthreads();
}

// ------------------------------- main kernel -------------------------------

__global__ __launch_bounds__(256, 1)
void fused_main(const float* __restrict__ gf, const float* __restrict__ med,
                const float* __restrict__ sml,
                const float* __restrict__ sm_b1, const float* __restrict__ sm_g,
                const float* __restrict__ sm_be,
                const float* __restrict__ mg_g,  const float* __restrict__ mg_be,
                const float* __restrict__ mg_b2,
                float* __restrict__ out){
    extern __shared__ float smem[];
    float*  gsum    = smem;                              // [64][260] fp32
    __half* ab0     = (__half*)(gsum + TM*GP);           // [64][72] fp16
    __half* ab1     = ab0 + TM*APH;
    __half* wb0     = ab1 + TM*APH;                      // 2 x [256][72] fp16
    __half* wb1     = wb0 + WBSZ;
    float*  prm     = (float*)(wb1 + WBSZ);              // 6 x 256
    float*  scratch = prm + 6*256;                       // 512

    const int tid  = threadIdx.x;
    const int lane = tid & 31, wid = tid >> 5;
    const int gid  = lane >> 2, tig = lane & 3;
    const int wm   = wid & 1,  wn  = wid >> 1;           // 2(M) x 4(N) warps
    const int row0 = blockIdx.x * TM;

    prm[tid]        = sm_b1[tid];
    prm[256 + tid]  = sm_g[tid];
    prm[512 + tid]  = sm_be[tid];
    prm[768 + tid]  = g_bias2[tid];
    prm[1024 + tid] = mg_g[tid];
    prm[1280 + tid] = mg_be[tid];
    for (int i = tid; i < TM*GP; i += 256) gsum[i] = 0.f;
    __syncthreads();

    const float4* S4s = (const float4*)sml;
    const float4* S4m = (const float4*)med;
    float d[2][8][4];

    // ---- MLP1 x4: gsum += gelu(LN(pool4(small)@W1 + b1))
#pragma unroll 1
    for (int m = 0; m < 4; m++){
        zero_d(d);
        gemm_pooled(d, S4s, c_adj[m][0], c_adj[m][1], c_adj[m][2], c_adj[m][3],
                    row0, g_W1h, ab0, ab1, wb0, wb1, wm, wn, gid, tig, tid);
        ln_gelu_reg<true>(d, gsum, scratch, prm, prm+256, prm+512, wm, wn, gid, tig);
    }

    // ---- h2 = mean(medium)@W1' + gsum@Cs (+bias2 in LN); g2 -> gsum
    zero_d(d);
    gemm_pooled(d, S4m, 0, 1, 2, 3, row0, g_W1ph,
                ab0, ab1, wb0, wb1, wm, wn, gid, tig, tid);
    gemm_smemA(d, gsum, g_Csh, HID, NCH2, wb0, wb1, wm, wn, gid, tig, tid);
    ln_gelu_reg<false>(d, gsum, scratch, prm+768, prm+1024, prm+1280, wm, wn, gid, tig);

    // ---- out = g2 @ W2' + global + mg_b2   (three 256-wide N passes)
#pragma unroll 1
    for (int np = 0; np < 3; np++){
        zero_d(d);
        gemm_smemA(d, gsum, g_W2ph + np*256*HID, HID, NCH2,
                   wb0, wb1, wm, wn, gid, tig, tid);
#pragma unroll
        for (int mt = 0; mt < 2; mt++)
#pragma unroll
        for (int nt = 0; nt < 8; nt++){
            int r  = wm*32 + mt*16 + gid;
            int c  = np*256 + wn*64 + nt*8 + tig*2;
            int ro = (row0 + r) * IN_DIM + c;
            float2 bv = *(const float2*)(mg_b2 + c);
            float2 gv = __ldcs((const float2*)(gf + ro));
            __stcs((float2*)(out + ro),
                   make_float2(d[mt][nt][0] + gv.x + bv.x,
                               d[mt][nt][1] + gv.y + bv.y));
            int ro8 = ro + 8*IN_DIM;
            float2 gv2 = __ldcs((const float2*)(gf + ro8));
            __stcs((float2*)(out + ro8),
                   make_float2(d[mt][nt][2] + gv2.x + bv.x,
                               d[mt][nt][3] + gv2.y + bv.y));
        }
    }
}

// ------------------------------- launcher ----------------------------------

extern "C" void kernel_launch(void* const* d_in, const int* in_sizes, int n_in,
                              void* d_out, int out_size){
    const float* gf   = (const float*)d_in[0];
    const float* med  = (const float*)d_in[1];
    const float* sml  = (const float*)d_in[2];
    const float* smw1 = (const float*)d_in[3];
    const float* smb1 = (const float*)d_in[4];
    const float* smg  = (const float*)d_in[5];
    const float* smbe = (const float*)d_in[6];
    const float* smw2 = (const float*)d_in[7];
    const float* smb2 = (const float*)d_in[8];
    const float* mgw1 = (const float*)d_in[9];
    const float* mgb1 = (const float*)d_in[10];
    const float* mgg  = (const float*)d_in[11];
    const float* mgbe = (const float*)d_in[12];
    const float* mgw2 = (const float*)d_in[13];
    const float* mgb2 = (const float*)d_in[14];
    float* out = (float*)d_out;
    (void)in_sizes; (void)n_in; (void)out_size;

    cudaFuncSetAttribute(fused_main, cudaFuncAttributeMaxDynamicSharedMemorySize, SMEM_BYTES);

    prep_transpose<<<IN_DIM, HID>>>(smw1, mgw1, mgw2);
    prep_C<<<HID, HID>>>(smw2, mgw1);
    prep_bias<<<1, HID>>>(smb2, mgw1, mgb1);
    fused_main<<<B_ROWS/TM, 256, SMEM_BYTES>>>(gf, med, sml, smb1, smg, smbe,
                                               mgg, mgbe, mgb2, out);
}